// round 15
// baseline (speedup 1.0000x reference)
#include <cuda_runtime.h>
#include <cuda_bf16.h>
#include <cuda_fp16.h>
#include <cstdint>

// ---------------------------------------------------------------------------
// Problem: B=16, S=512, F=512, H=8, D=512.
// Logit path (Q,K proj; qk): bf16 hi/lo 3-term emulation, warp tile 64x32,
//   CTA 128x128, 2 CTAs/SM (smem-crossbar optimized: 128B reads/MMA).
// V path: single-pass fp16 proj (fused transpose) + 1-pass fp16 PV.
// ---------------------------------------------------------------------------
__device__ float g_P[128 * 512 * 512];      // scores fp32 (softmax input)

__device__ __nv_bfloat16 g_xh[8192 * 512],      g_xl[8192 * 512];
__device__ __nv_bfloat16 g_WTh[2 * 4096 * 512], g_WTl[2 * 4096 * 512]; // wq,wk
__device__ __nv_bfloat16 g_Qh[8192 * 4096],     g_Ql[8192 * 4096];
__device__ __nv_bfloat16 g_Kh[8192 * 4096],     g_Kl[8192 * 4096];

__device__ __half g_x16[8192 * 512];        // x, single fp16 plane
__device__ __half g_WV16[4096 * 512];       // wv^T, single fp16 plane
__device__ __half g_VT[128 * 512 * 512];    // V^T per (h,b): [z][d][j], fp16
__device__ __half g_Pf[128 * 512 * 512];    // softmax probs fp16

// ===========================================================================
// Helpers
// ===========================================================================
__device__ __forceinline__ uint32_t smem_u32(const void* p) {
    uint32_t a;
    asm("{ .reg .u64 t; cvta.to.shared.u64 t, %1; cvt.u32.u64 %0, t; }"
        : "=r"(a) : "l"(p));
    return a;
}

__device__ __forceinline__ void cp16(uint32_t dst, const void* src) {
    asm volatile("cp.async.cg.shared.global [%0], [%1], 16;"
                 :: "r"(dst), "l"(src) : "memory");
}
#define CP_COMMIT() asm volatile("cp.async.commit_group;" ::: "memory")
#define CP_WAIT1()  asm volatile("cp.async.wait_group 1;" ::: "memory")

// pack two fp32 into bf16x2 hi-plane word + lo-plane word (rn rounding)
__device__ __forceinline__ void pack2(float x0, float x1, uint32_t& h, uint32_t& l) {
    asm("cvt.rn.bf16x2.f32 %0, %1, %2;" : "=r"(h) : "f"(x1), "f"(x0));
    float f0 = __uint_as_float(h << 16);
    float f1 = __uint_as_float(h & 0xFFFF0000u);
    float l0 = x0 - f0, l1 = x1 - f1;
    asm("cvt.rn.bf16x2.f32 %0, %1, %2;" : "=r"(l) : "f"(l1), "f"(l0));
}

// D += A * B : m16n8k16 bf16, row.col, fp32 accumulate
__device__ __forceinline__ void mma16(float* c, const uint32_t* a, const uint32_t* b) {
    asm volatile(
        "mma.sync.aligned.m16n8k16.row.col.f32.bf16.bf16.f32 "
        "{%0,%1,%2,%3}, {%4,%5,%6,%7}, {%8,%9}, {%0,%1,%2,%3};"
        : "+f"(c[0]), "+f"(c[1]), "+f"(c[2]), "+f"(c[3])
        : "r"(a[0]), "r"(a[1]), "r"(a[2]), "r"(a[3]), "r"(b[0]), "r"(b[1]));
}

// D += A * B : m16n8k16 fp16, row.col, fp32 accumulate
__device__ __forceinline__ void mma16f(float* c, const uint32_t* a, const uint32_t* b) {
    asm volatile(
        "mma.sync.aligned.m16n8k16.row.col.f32.f16.f16.f32 "
        "{%0,%1,%2,%3}, {%4,%5,%6,%7}, {%8,%9}, {%0,%1,%2,%3};"
        : "+f"(c[0]), "+f"(c[1]), "+f"(c[2]), "+f"(c[3])
        : "r"(a[0]), "r"(a[1]), "r"(a[2]), "r"(a[3]), "r"(b[0]), "r"(b[1]));
}

__device__ __forceinline__ void ldsm4(uint32_t* r, uint32_t addr) {
    asm volatile("ldmatrix.sync.aligned.m8n8.x4.shared.b16 {%0,%1,%2,%3}, [%4];"
                 : "=r"(r[0]), "=r"(r[1]), "=r"(r[2]), "=r"(r[3]) : "r"(addr));
}

// ===========================================================================
// bf16 3-term NT GEMM, 256 threads, CTA 128x128, warp tile 64x32 (2M x 4N).
// Stage (KB=32): A rows 0..127 @ [0,16K), B rows 0..127 @ [16K,32K);
// row = 128B (hi 64 | lo 64), chunk swizzle c^(row&7). 3 stages = 96KB.
// 2 CTAs/SM. Single-buffered B-lo reload keeps regs ~120.
// ===========================================================================
#define KB        32
#define NKB       16
#define STAGE3    32768
#define GEMM_SMEM (3 * STAGE3)   // 98304

#define F16_STAGE 24576
#define PV_SMEM   (3 * F16_STAGE) // 73728

template <int EPI>   // 0: fp32 C ; 1: bf16 hi/lo planes
__device__ __forceinline__ void gemm_nt_bf16(
    const __nv_bfloat16* __restrict__ Ah, const __nv_bfloat16* __restrict__ Al, int lda,
    const __nv_bfloat16* __restrict__ Bh, const __nv_bfloat16* __restrict__ Bl, int ldb,
    float* __restrict__ C, __nv_bfloat16* __restrict__ Ch,
    __nv_bfloat16* __restrict__ Cl, int ldc, int by, int bx)
{
    extern __shared__ __align__(128) char smc[];
    const uint32_t sa = smem_u32(smc);

    const int tid = threadIdx.x;
    const int wid = tid >> 5;
    const int lid = tid & 31;
    const int wr  = wid >> 2;          // 0..1 (M, 64 rows each)
    const int wc  = wid & 3;           // 0..3 (N, 32 cols each)
    const int g   = lid >> 2;
    const int tg  = lid & 3;

    const __nv_bfloat16* Abh = Ah + (size_t)(by * 128) * lda;
    const __nv_bfloat16* Abl = Al + (size_t)(by * 128) * lda;
    const __nv_bfloat16* Bbh = Bh + (size_t)(bx * 128) * ldb;
    const __nv_bfloat16* Bbl = Bl + (size_t)(bx * 128) * ldb;

    auto load_stage = [&](int buf, int kb) {
        const uint32_t dbase = sa + buf * STAGE3;
        const int kc = kb * KB;
#pragma unroll
        for (int i = 0; i < 4; ++i) {               // A: 1024 chunks
            const int t = tid + (i << 8);
            const int row = t >> 3, c = t & 7;
            const __nv_bfloat16* src =
                ((c & 4) ? Abl : Abh) + (size_t)row * lda + kc + (c & 3) * 8;
            cp16(dbase + row * 128 + ((c ^ (row & 7)) << 4), src);
        }
#pragma unroll
        for (int i = 0; i < 4; ++i) {               // B: 1024 chunks
            const int t = tid + (i << 8);
            const int row = t >> 3, c = t & 7;
            const __nv_bfloat16* src =
                ((c & 4) ? Bbl : Bbh) + (size_t)row * ldb + kc + (c & 3) * 8;
            cp16(dbase + 16384 + row * 128 + ((c ^ (row & 7)) << 4), src);
        }
    };

    float acc[4][4][4];
#pragma unroll
    for (int mt = 0; mt < 4; ++mt)
#pragma unroll
        for (int nt = 0; nt < 4; ++nt)
#pragma unroll
            for (int i = 0; i < 4; ++i) acc[mt][nt][i] = 0.0f;

    const uint32_t sx = (uint32_t)(lid & 7) << 4;
    const uint32_t hb = (uint32_t)(lid >> 4) << 4;
    uint32_t ra[4], rb[2];
#pragma unroll
    for (int mt = 0; mt < 4; ++mt)
        ra[mt] = (uint32_t)(wr * 64 + mt * 16 + (lid & 15)) * 128;
#pragma unroll
    for (int n2 = 0; n2 < 2; ++n2)
        rb[n2] = 16384u + (uint32_t)(wc * 32 + n2 * 16 + (lid & 15)) * 128;

    load_stage(0, 0); CP_COMMIT();
    load_stage(1, 1); CP_COMMIT();

#pragma unroll 1
    for (int kb = 0; kb < NKB; ++kb) {
        CP_WAIT1();
        __syncthreads();
        if (kb + 2 < NKB) load_stage((kb + 2) % 3, kb + 2);
        CP_COMMIT();

        const uint32_t sbase = sa + (kb % 3) * STAGE3;

#pragma unroll
        for (int ks = 0; ks < 2; ++ks) {
            const uint32_t cvh = (uint32_t)(ks << 5) + hb;
            const uint32_t cvl = cvh + 64;

            uint32_t ah[4][4], al[4][4], bb[4][2];
#pragma unroll
            for (int mt = 0; mt < 4; ++mt) {
                ldsm4(ah[mt], sbase + ra[mt] + (cvh ^ sx));
                ldsm4(al[mt], sbase + ra[mt] + (cvl ^ sx));
            }
            // ---- B hi ----
#pragma unroll
            for (int n2 = 0; n2 < 2; ++n2) {
                uint32_t r[4];
                ldsm4(r, sbase + rb[n2] + (cvh ^ sx));
                bb[n2 * 2][0] = r[0]; bb[n2 * 2][1] = r[2];
                bb[n2 * 2 + 1][0] = r[1]; bb[n2 * 2 + 1][1] = r[3];
            }
#pragma unroll
            for (int mt = 0; mt < 4; ++mt)
#pragma unroll
                for (int nt = 0; nt < 4; ++nt) mma16(acc[mt][nt], ah[mt], bb[nt]);
#pragma unroll
            for (int mt = 0; mt < 4; ++mt)
#pragma unroll
                for (int nt = 0; nt < 4; ++nt) mma16(acc[mt][nt], al[mt], bb[nt]);
            // ---- B lo (reuse regs) ----
#pragma unroll
            for (int n2 = 0; n2 < 2; ++n2) {
                uint32_t r[4];
                ldsm4(r, sbase + rb[n2] + (cvl ^ sx));
                bb[n2 * 2][0] = r[0]; bb[n2 * 2][1] = r[2];
                bb[n2 * 2 + 1][0] = r[1]; bb[n2 * 2 + 1][1] = r[3];
            }
#pragma unroll
            for (int mt = 0; mt < 4; ++mt)
#pragma unroll
                for (int nt = 0; nt < 4; ++nt) mma16(acc[mt][nt], ah[mt], bb[nt]);
        }
    }

    const int rbase = by * 128 + wr * 64 + g;
    const int cbase = bx * 128 + wc * 32 + tg * 2;
#pragma unroll
    for (int mt = 0; mt < 4; ++mt) {
#pragma unroll
        for (int nt = 0; nt < 4; ++nt) {
            const int r = rbase + mt * 16;
            const int c = cbase + nt * 8;
            if (EPI == 0) {
                *reinterpret_cast<float2*>(&C[(size_t)r * ldc + c]) =
                    make_float2(acc[mt][nt][0], acc[mt][nt][1]);
                *reinterpret_cast<float2*>(&C[(size_t)(r + 8) * ldc + c]) =
                    make_float2(acc[mt][nt][2], acc[mt][nt][3]);
            } else {
                uint32_t h, l;
                pack2(acc[mt][nt][0], acc[mt][nt][1], h, l);
                *reinterpret_cast<uint32_t*>(Ch + (size_t)r * ldc + c) = h;
                *reinterpret_cast<uint32_t*>(Cl + (size_t)r * ldc + c) = l;
                pack2(acc[mt][nt][2], acc[mt][nt][3], h, l);
                *reinterpret_cast<uint32_t*>(Ch + (size_t)(r + 8) * ldc + c) = h;
                *reinterpret_cast<uint32_t*>(Cl + (size_t)(r + 8) * ldc + c) = l;
            }
        }
    }
}

// ===========================================================================
// fp16 single-pass NT GEMM body (proj_v / pv). C tile 128x64. [R14 core]
// KB=64, stage 24KB (A 128 rows @0, B 64 rows @16K), 3 stages.
// EPI: 0 -> fp32 C (pv) ; 1 -> fused-transpose fp16 VT write (proj_v)
// ===========================================================================
template <int EPI>
__device__ __forceinline__ void gemm_nt_f16(
    const __half* __restrict__ Ab, const __half* __restrict__ Bb,
    float* __restrict__ C, int ldc, __half* __restrict__ VT,
    int rloc0, int cloc0)
{
    extern __shared__ __align__(128) char smc[];
    const uint32_t sa = smem_u32(smc);

    const int tid = threadIdx.x;
    const int wid = tid >> 5;
    const int lid = tid & 31;
    const int wr  = wid >> 1;
    const int wc  = wid & 1;
    const int g   = lid >> 2;
    const int tg  = lid & 3;

    auto load_stage = [&](int buf, int kb) {
        const uint32_t dbase = sa + buf * F16_STAGE;
        const int kc = kb * 64;
#pragma unroll
        for (int i = 0; i < 4; ++i) {               // A: 1024 chunks
            const int t = tid + (i << 8);
            const int row = t >> 3, c = t & 7;
            cp16(dbase + row * 128 + ((c ^ (row & 7)) << 4),
                 Ab + (size_t)row * 512 + kc + c * 8);
        }
        {                                            // B: 512 chunks
            const int t = tid;
            const int row = t >> 3, c = t & 7;
            cp16(dbase + 16384 + row * 128 + ((c ^ (row & 7)) << 4),
                 Bb + (size_t)row * 512 + kc + c * 8);
        }
        {
            const int t = tid + 256;
            const int row = t >> 3, c = t & 7;
            cp16(dbase + 16384 + row * 128 + ((c ^ (row & 7)) << 4),
                 Bb + (size_t)row * 512 + kc + c * 8);
        }
    };

    float acc[2][4][4];
#pragma unroll
    for (int mt = 0; mt < 2; ++mt)
#pragma unroll
        for (int nt = 0; nt < 4; ++nt)
#pragma unroll
            for (int i = 0; i < 4; ++i) acc[mt][nt][i] = 0.0f;

    const uint32_t sx = (uint32_t)(lid & 7) << 4;
    const uint32_t hb = (uint32_t)(lid >> 4) << 4;
    uint32_t ra[2], rb[2];
#pragma unroll
    for (int mt = 0; mt < 2; ++mt)
        ra[mt] = (uint32_t)(wr * 32 + mt * 16 + (lid & 15)) * 128;
#pragma unroll
    for (int n2 = 0; n2 < 2; ++n2)
        rb[n2] = 16384u + (uint32_t)(wc * 32 + n2 * 16 + (lid & 15)) * 128;

    load_stage(0, 0); CP_COMMIT();
    load_stage(1, 1); CP_COMMIT();

#pragma unroll 1
    for (int kb = 0; kb < 8; ++kb) {
        CP_WAIT1();
        __syncthreads();
        if (kb + 2 < 8) load_stage((kb + 2) % 3, kb + 2);
        CP_COMMIT();

        const uint32_t sbase = sa + (kb % 3) * F16_STAGE;

#pragma unroll
        for (int ks = 0; ks < 4; ++ks) {
            const uint32_t cv = (uint32_t)(ks << 5) + hb;

            uint32_t ah[2][4], bb[4][2];
#pragma unroll
            for (int mt = 0; mt < 2; ++mt)
                ldsm4(ah[mt], sbase + ra[mt] + (cv ^ sx));
#pragma unroll
            for (int n2 = 0; n2 < 2; ++n2) {
                uint32_t r[4];
                ldsm4(r, sbase + rb[n2] + (cv ^ sx));
                bb[n2 * 2][0] = r[0]; bb[n2 * 2][1] = r[2];
                bb[n2 * 2 + 1][0] = r[1]; bb[n2 * 2 + 1][1] = r[3];
            }
#pragma unroll
            for (int mt = 0; mt < 2; ++mt)
#pragma unroll
                for (int nt = 0; nt < 4; ++nt) mma16f(acc[mt][nt], ah[mt], bb[nt]);
        }
    }

    const int rbase = rloc0 + wr * 32 + g;
    const int cbase = cloc0 + wc * 32 + tg * 2;
#pragma unroll
    for (int mt = 0; mt < 2; ++mt) {
#pragma unroll
        for (int nt = 0; nt < 4; ++nt) {
            const int r = rbase + mt * 16;
            const int c = cbase + nt * 8;
            if (EPI == 0) {
                *reinterpret_cast<float2*>(&C[(size_t)r * ldc + c]) =
                    make_float2(acc[mt][nt][0], acc[mt][nt][1]);
                *reinterpret_cast<float2*>(&C[(size_t)(r + 8) * ldc + c]) =
                    make_float2(acc[mt][nt][2], acc[mt][nt][3]);
            } else {
                __half2 v0 = __floats2half2_rn(acc[mt][nt][0], acc[mt][nt][1]);
                __half2 v1 = __floats2half2_rn(acc[mt][nt][2], acc[mt][nt][3]);
                *reinterpret_cast<__half2*>(VT + (size_t)r * 512 + c)       = v0;
                *reinterpret_cast<__half2*>(VT + (size_t)(r + 8) * 512 + c) = v1;
            }
        }
    }
}

// ===========================================================================
// Q,K projections (bf16 3-term, new 128x128 tiles)
// ===========================================================================
__global__ void __launch_bounds__(256, 2)
proj_mm()
{
    const int z = blockIdx.z;                 // 0:Q 1:K
    const __nv_bfloat16* Bh = g_WTh + (size_t)z * 4096 * 512;
    const __nv_bfloat16* Bl = g_WTl + (size_t)z * 4096 * 512;
    if (z == 0)
        gemm_nt_bf16<1>(g_xh, g_xl, 512, Bh, Bl, 512, nullptr, g_Qh, g_Ql, 4096,
                        blockIdx.y, blockIdx.x);
    else
        gemm_nt_bf16<1>(g_xh, g_xl, 512, Bh, Bl, 512, nullptr, g_Kh, g_Kl, 4096,
                        blockIdx.y, blockIdx.x);
}

// ===========================================================================
// Merged launch (1-D grid of 6144): id<2048 -> qk 128x128 tile;
// id>=2048 -> proj_v fp16 tile (independent work, overlapping tails).
// ===========================================================================
__global__ void __launch_bounds__(256, 2)
qk_projv()
{
    const int id = blockIdx.x;
    if (id < 2048) {
        const int z  = id >> 4;               // h*16 + b
        const int by = (id >> 2) & 3;
        const int bx = id & 3;
        const int h = z >> 4, b = z & 15;
        const size_t off = (size_t)b * 512 * 4096 + h * 512;
        gemm_nt_bf16<0>(g_Qh + off, g_Ql + off, 4096,
                        g_Kh + off, g_Kl + off, 4096,
                        g_P + (size_t)z * 512 * 512, nullptr, nullptr, 512,
                        by, bx);
    } else {
        const int t  = id - 2048;             // 0..4095
        const int vx = t & 127;               // token-tile (64 tokens)
        const int vy = t >> 7;                // d-tile (128 dcols)
        const __half* Ab = g_WV16 + (size_t)vy * 128 * 512;
        const __half* Bb = g_x16  + (size_t)vx * 64 * 512;
        const int hH = vy >> 2, bB = vx >> 3;
        __half* VT = g_VT + (size_t)(hH * 16 + bB) * 262144;
        gemm_nt_f16<1>(Ab, Bb, nullptr, 0, VT,
                       (vy & 3) * 128, (vx & 7) * 64);
    }
}

// ===========================================================================
// PV GEMM: single fp16 P x single fp16 V, 1 MMA pass. C[128x64] fp32.
// ===========================================================================
__global__ void __launch_bounds__(256, 3)
pv_mm(float* __restrict__ out)
{
    const int z = blockIdx.z;
    const int h = z >> 4, b = z & 15;
    const size_t zo = (size_t)z * 262144;
    const __half* Ab = g_Pf + zo + (size_t)(blockIdx.y * 128) * 512;
    const __half* Bb = g_VT + zo + (size_t)(blockIdx.x * 64) * 512;
    float* C = out + (size_t)b * 512 * 4096 + h * 512;
    gemm_nt_f16<0>(Ab, Bb, C, 4096, nullptr,
                   blockIdx.y * 128, blockIdx.x * 64);
}

// ===========================================================================
// Prep kernels
// ===========================================================================
__global__ void split_x(const float* __restrict__ x)
{
    const size_t i = ((size_t)blockIdx.x * 256 + threadIdx.x) * 4;
    const float4 v = *reinterpret_cast<const float4*>(x + i);
    uint32_t h0, l0, h1, l1;
    pack2(v.x, v.y, h0, l0);
    pack2(v.z, v.w, h1, l1);
    *reinterpret_cast<uint2*>(g_xh + i) = make_uint2(h0, h1);
    *reinterpret_cast<uint2*>(g_xl + i) = make_uint2(l0, l1);
    __half2 a = __floats2half2_rn(v.x, v.y);
    __half2 b = __floats2half2_rn(v.z, v.w);
    *reinterpret_cast<__half2*>(g_x16 + i)     = a;
    *reinterpret_cast<__half2*>(g_x16 + i + 2) = b;
}

// z=0: wq (bf16 planes), z=1: wk (bf16 planes), z=2: wv (fp16 single)
__global__ void wt_all(const float* __restrict__ wq,
                       const float* __restrict__ wk,
                       const float* __restrict__ wv)
{
    __shared__ float t[32][33];
    const int z = blockIdx.z;
    const float* W = (z == 0) ? wq : (z == 1) ? wk : wv;   // [512, 4096]
    const int n0 = blockIdx.x * 32, k0 = blockIdx.y * 32;
    const int tx = threadIdx.x, ty = threadIdx.y;
#pragma unroll
    for (int i = 0; i < 4; ++i)
        t[ty + i * 8][tx] = W[(size_t)(k0 + ty + i * 8) * 4096 + n0 + tx];
    __syncthreads();
    if (z < 2) {
        __nv_bfloat16* WTh = g_WTh + (size_t)z * 4096 * 512;
        __nv_bfloat16* WTl = g_WTl + (size_t)z * 4096 * 512;
#pragma unroll
        for (int i = 0; i < 4; ++i) {
            const float v = t[tx][ty + i * 8];
            const __nv_bfloat16 hbf = __float2bfloat16_rn(v);
            const float lo = v - __bfloat162float(hbf);
            const size_t idx = (size_t)(n0 + ty + i * 8) * 512 + k0 + tx;
            WTh[idx] = hbf;
            WTl[idx] = __float2bfloat16_rn(lo);
        }
    } else {
#pragma unroll
        for (int i = 0; i < 4; ++i) {
            const float v = t[tx][ty + i * 8];
            g_WV16[(size_t)(n0 + ty + i * 8) * 512 + k0 + tx] = __float2half_rn(v);
        }
    }
}

// ===========================================================================
// Softmax over rows of g_P (512 wide), writes single fp16 plane g_Pf.
// ===========================================================================
__global__ void softmax_kernel()
{
    const size_t row = blockIdx.x;
    const float* p = g_P + row * 512;
    const int t = threadIdx.x;

    float2 v = reinterpret_cast<const float2*>(p)[t];
    __shared__ float red[8];

    float m = fmaxf(v.x, v.y);
#pragma unroll
    for (int o = 16; o > 0; o >>= 1) m = fmaxf(m, __shfl_xor_sync(0xFFFFFFFFu, m, o));
    if ((t & 31) == 0) red[t >> 5] = m;
    __syncthreads();
    m = red[0];
#pragma unroll
    for (int i = 1; i < 8; i++) m = fmaxf(m, red[i]);
    __syncthreads();

    const float e0 = __expf(v.x - m);
    const float e1 = __expf(v.y - m);

    float s = e0 + e1;
#pragma unroll
    for (int o = 16; o > 0; o >>= 1) s += __shfl_xor_sync(0xFFFFFFFFu, s, o);
    if ((t & 31) == 0) red[t >> 5] = s;
    __syncthreads();
    s = red[0];
#pragma unroll
    for (int i = 1; i < 8; i++) s += red[i];

    const float inv = 1.0f / s;
    reinterpret_cast<__half2*>(g_Pf + row * 512)[t] =
        __floats2half2_rn(e0 * inv, e1 * inv);
}

// ===========================================================================
// Launch
// ===========================================================================
extern "C" void kernel_launch(void* const* d_in, const int* in_sizes, int n_in,
                              void* d_out, int out_size)
{
    const float* x  = (const float*)d_in[0];
    const float* wq = (const float*)d_in[1];
    const float* wk = (const float*)d_in[2];
    const float* wv = (const float*)d_in[3];
    float* out = (float*)d_out;

    cudaFuncSetAttribute(proj_mm,  cudaFuncAttributeMaxDynamicSharedMemorySize, GEMM_SMEM);
    cudaFuncSetAttribute(qk_projv, cudaFuncAttributeMaxDynamicSharedMemorySize, GEMM_SMEM);
    cudaFuncSetAttribute(pv_mm,    cudaFuncAttributeMaxDynamicSharedMemorySize, PV_SMEM);

    split_x<<<4096, 256>>>(x);                                   // 1
    wt_all<<<dim3(128, 16, 3), dim3(32, 8)>>>(wq, wk, wv);       // 2
    proj_mm<<<dim3(32, 64, 2), 256, GEMM_SMEM>>>();              // 3
    qk_projv<<<6144, 256, GEMM_SMEM>>>();                        // 4 <- profiled
    softmax_kernel<<<65536, 256>>>();                            // 5
    pv_mm<<<dim3(8, 4, 128), 256, PV_SMEM>>>(out);               // 6
}

// round 16
// speedup vs baseline: 1.3135x; 1.3135x over previous
#include <cuda_runtime.h>
#include <cuda_bf16.h>
#include <cuda_fp16.h>
#include <cstdint>

// ---------------------------------------------------------------------------
// Problem: B=16, S=512, F=512, H=8, D=512.
// Logit path (restructured): GT_h = Wk_h x Wq_h^T per head; Y_z = x_b GT_h^T;
//   logits_z = Y_z x_b^T. All bf16 hi/lo 3-term. MMA count -31% vs Q/K proj.
// V path: single-pass fp16 proj (fused transpose) + 1-pass fp16 PV.
// ---------------------------------------------------------------------------
__device__ float g_P[128 * 512 * 512];      // scores fp32 (softmax input)

__device__ __nv_bfloat16 g_xh[8192 * 512],   g_xl[8192 * 512];
__device__ __nv_bfloat16 g_wqh[512 * 4096],  g_wql[512 * 4096];
__device__ __nv_bfloat16 g_wkh[512 * 4096],  g_wkl[512 * 4096];
__device__ __nv_bfloat16 g_GTh[8 * 512 * 512],   g_GTl[8 * 512 * 512];
__device__ __nv_bfloat16 g_Yh[128 * 512 * 512],  g_Yl[128 * 512 * 512];

__device__ __half g_x16[8192 * 512];        // x, single fp16 plane
__device__ __half g_WV16[4096 * 512];       // wv^T, single fp16 plane
__device__ __half g_VT[128 * 512 * 512];    // V^T per (h,b): [z][d][j], fp16
__device__ __half g_Pf[128 * 512 * 512];    // softmax probs fp16

// ===========================================================================
// Helpers
// ===========================================================================
__device__ __forceinline__ uint32_t smem_u32(const void* p) {
    uint32_t a;
    asm("{ .reg .u64 t; cvta.to.shared.u64 t, %1; cvt.u32.u64 %0, t; }"
        : "=r"(a) : "l"(p));
    return a;
}

__device__ __forceinline__ void cp16(uint32_t dst, const void* src) {
    asm volatile("cp.async.cg.shared.global [%0], [%1], 16;"
                 :: "r"(dst), "l"(src) : "memory");
}
#define CP_COMMIT() asm volatile("cp.async.commit_group;" ::: "memory")
#define CP_WAIT1()  asm volatile("cp.async.wait_group 1;" ::: "memory")

// pack two fp32 into bf16x2 hi-plane word + lo-plane word (rn rounding)
__device__ __forceinline__ void pack2(float x0, float x1, uint32_t& h, uint32_t& l) {
    asm("cvt.rn.bf16x2.f32 %0, %1, %2;" : "=r"(h) : "f"(x1), "f"(x0));
    float f0 = __uint_as_float(h << 16);
    float f1 = __uint_as_float(h & 0xFFFF0000u);
    float l0 = x0 - f0, l1 = x1 - f1;
    asm("cvt.rn.bf16x2.f32 %0, %1, %2;" : "=r"(l) : "f"(l1), "f"(l0));
}

// D += A * B : m16n8k16 bf16, row.col, fp32 accumulate
__device__ __forceinline__ void mma16(float* c, const uint32_t* a, const uint32_t* b) {
    asm volatile(
        "mma.sync.aligned.m16n8k16.row.col.f32.bf16.bf16.f32 "
        "{%0,%1,%2,%3}, {%4,%5,%6,%7}, {%8,%9}, {%0,%1,%2,%3};"
        : "+f"(c[0]), "+f"(c[1]), "+f"(c[2]), "+f"(c[3])
        : "r"(a[0]), "r"(a[1]), "r"(a[2]), "r"(a[3]), "r"(b[0]), "r"(b[1]));
}

// D += A * B : m16n8k16 fp16, row.col, fp32 accumulate
__device__ __forceinline__ void mma16f(float* c, const uint32_t* a, const uint32_t* b) {
    asm volatile(
        "mma.sync.aligned.m16n8k16.row.col.f32.f16.f16.f32 "
        "{%0,%1,%2,%3}, {%4,%5,%6,%7}, {%8,%9}, {%0,%1,%2,%3};"
        : "+f"(c[0]), "+f"(c[1]), "+f"(c[2]), "+f"(c[3])
        : "r"(a[0]), "r"(a[1]), "r"(a[2]), "r"(a[3]), "r"(b[0]), "r"(b[1]));
}

__device__ __forceinline__ void ldsm4(uint32_t* r, uint32_t addr) {
    asm volatile("ldmatrix.sync.aligned.m8n8.x4.shared.b16 {%0,%1,%2,%3}, [%4];"
                 : "=r"(r[0]), "=r"(r[1]), "=r"(r[2]), "=r"(r[3]) : "r"(addr));
}

// ===========================================================================
// NT GEMM on bf16 hi/lo planes (3-term emulation), 256 threads. [R10 core]
//   C[128x64] tile, 8 warps 4(M)x2(N), warp tile 32x32, 3 CTAs/SM. K=512.
// ===========================================================================
#define KB        32
#define NKB       16
#define STAGE     24576
#define GEMM_SMEM (3 * STAGE)   // 73728

template <int EPI>   // 0: fp32 C ; 1: bf16 hi/lo planes
__device__ __forceinline__ void gemm_nt_bf16(
    const __nv_bfloat16* __restrict__ Ah, const __nv_bfloat16* __restrict__ Al, int lda,
    const __nv_bfloat16* __restrict__ Bh, const __nv_bfloat16* __restrict__ Bl, int ldb,
    float* __restrict__ C, __nv_bfloat16* __restrict__ Ch,
    __nv_bfloat16* __restrict__ Cl, int ldc, int by, int bx)
{
    extern __shared__ __align__(128) char smc[];
    const uint32_t sa = smem_u32(smc);

    const int tid = threadIdx.x;
    const int wid = tid >> 5;
    const int lid = tid & 31;
    const int wr  = wid >> 1;          // 0..3 (M)
    const int wc  = wid & 1;           // 0..1 (N)
    const int g   = lid >> 2;
    const int tg  = lid & 3;

    const __nv_bfloat16* Abh = Ah + (size_t)(by * 128) * lda;
    const __nv_bfloat16* Abl = Al + (size_t)(by * 128) * lda;
    const __nv_bfloat16* Bbh = Bh + (size_t)(bx * 64) * ldb;
    const __nv_bfloat16* Bbl = Bl + (size_t)(bx * 64) * ldb;

    auto load_stage = [&](int buf, int kb) {
        const uint32_t dbase = sa + buf * STAGE;
        const int kc = kb * KB;
#pragma unroll
        for (int i = 0; i < 4; ++i) {               // A: 1024 chunks
            const int t = tid + (i << 8);
            const int row = t >> 3, c = t & 7;
            const __nv_bfloat16* src =
                ((c & 4) ? Abl : Abh) + (size_t)row * lda + kc + (c & 3) * 8;
            cp16(dbase + row * 128 + ((c ^ (row & 7)) << 4), src);
        }
        {
            const int t = tid + 1024;
            const int row = (t >> 3) & 63, c = t & 7;
            const __nv_bfloat16* src =
                ((c & 4) ? Bbl : Bbh) + (size_t)row * ldb + kc + (c & 3) * 8;
            cp16(dbase + 16384 + row * 128 + ((c ^ (row & 7)) << 4), src);
        }
        {
            const int t = tid + 1280;
            const int row = (t >> 3) & 63, c = t & 7;
            const __nv_bfloat16* src =
                ((c & 4) ? Bbl : Bbh) + (size_t)row * ldb + kc + (c & 3) * 8;
            cp16(dbase + 16384 + row * 128 + ((c ^ (row & 7)) << 4), src);
        }
    };

    float acc[2][4][4];
#pragma unroll
    for (int mt = 0; mt < 2; ++mt)
#pragma unroll
        for (int nt = 0; nt < 4; ++nt)
#pragma unroll
            for (int i = 0; i < 4; ++i) acc[mt][nt][i] = 0.0f;

    const uint32_t sx = (uint32_t)(lid & 7) << 4;
    const uint32_t hb = (uint32_t)(lid >> 4) << 4;
    uint32_t ra[2], rb[2];
#pragma unroll
    for (int mt = 0; mt < 2; ++mt)
        ra[mt] = (uint32_t)(wr * 32 + mt * 16 + (lid & 15)) * 128;
#pragma unroll
    for (int n2 = 0; n2 < 2; ++n2)
        rb[n2] = 16384u + (uint32_t)(wc * 32 + n2 * 16 + (lid & 15)) * 128;

    load_stage(0, 0); CP_COMMIT();
    load_stage(1, 1); CP_COMMIT();

#pragma unroll 1
    for (int kb = 0; kb < NKB; ++kb) {
        CP_WAIT1();
        __syncthreads();
        if (kb + 2 < NKB) load_stage((kb + 2) % 3, kb + 2);
        CP_COMMIT();

        const uint32_t sbase = sa + (kb % 3) * STAGE;

#pragma unroll
        for (int ks = 0; ks < 2; ++ks) {
            const uint32_t cvh = (uint32_t)(ks << 5) + hb;
            const uint32_t cvl = cvh + 64;

            uint32_t ah[2][4], al[2][4], bb[4][2];
#pragma unroll
            for (int mt = 0; mt < 2; ++mt) {
                ldsm4(ah[mt], sbase + ra[mt] + (cvh ^ sx));
                ldsm4(al[mt], sbase + ra[mt] + (cvl ^ sx));
            }
#pragma unroll
            for (int n2 = 0; n2 < 2; ++n2) {
                uint32_t r[4];
                ldsm4(r, sbase + rb[n2] + (cvh ^ sx));
                bb[n2 * 2][0] = r[0]; bb[n2 * 2][1] = r[2];
                bb[n2 * 2 + 1][0] = r[1]; bb[n2 * 2 + 1][1] = r[3];
            }
#pragma unroll
            for (int mt = 0; mt < 2; ++mt)
#pragma unroll
                for (int nt = 0; nt < 4; ++nt) mma16(acc[mt][nt], ah[mt], bb[nt]);
#pragma unroll
            for (int mt = 0; mt < 2; ++mt)
#pragma unroll
                for (int nt = 0; nt < 4; ++nt) mma16(acc[mt][nt], al[mt], bb[nt]);
#pragma unroll
            for (int n2 = 0; n2 < 2; ++n2) {
                uint32_t r[4];
                ldsm4(r, sbase + rb[n2] + (cvl ^ sx));
                bb[n2 * 2][0] = r[0]; bb[n2 * 2][1] = r[2];
                bb[n2 * 2 + 1][0] = r[1]; bb[n2 * 2 + 1][1] = r[3];
            }
#pragma unroll
            for (int mt = 0; mt < 2; ++mt)
#pragma unroll
                for (int nt = 0; nt < 4; ++nt) mma16(acc[mt][nt], ah[mt], bb[nt]);
        }
    }

    const int rbase = by * 128 + wr * 32 + g;
    const int cbase = bx * 64 + wc * 32 + tg * 2;
#pragma unroll
    for (int mt = 0; mt < 2; ++mt) {
#pragma unroll
        for (int nt = 0; nt < 4; ++nt) {
            const int r = rbase + mt * 16;
            const int c = cbase + nt * 8;
            if (EPI == 0) {
                *reinterpret_cast<float2*>(&C[(size_t)r * ldc + c]) =
                    make_float2(acc[mt][nt][0], acc[mt][nt][1]);
                *reinterpret_cast<float2*>(&C[(size_t)(r + 8) * ldc + c]) =
                    make_float2(acc[mt][nt][2], acc[mt][nt][3]);
            } else {
                uint32_t h, l;
                pack2(acc[mt][nt][0], acc[mt][nt][1], h, l);
                *reinterpret_cast<uint32_t*>(Ch + (size_t)r * ldc + c) = h;
                *reinterpret_cast<uint32_t*>(Cl + (size_t)r * ldc + c) = l;
                pack2(acc[mt][nt][2], acc[mt][nt][3], h, l);
                *reinterpret_cast<uint32_t*>(Ch + (size_t)(r + 8) * ldc + c) = h;
                *reinterpret_cast<uint32_t*>(Cl + (size_t)(r + 8) * ldc + c) = l;
            }
        }
    }
}

// ===========================================================================
// fp16 single-pass NT GEMM body (proj_v / pv). C tile 128x64. [R14 core]
// ===========================================================================
template <int EPI>
__device__ __forceinline__ void gemm_nt_f16(
    const __half* __restrict__ Ab, const __half* __restrict__ Bb,
    float* __restrict__ C, int ldc, __half* __restrict__ VT,
    int rloc0, int cloc0)
{
    extern __shared__ __align__(128) char smc[];
    const uint32_t sa = smem_u32(smc);

    const int tid = threadIdx.x;
    const int wid = tid >> 5;
    const int lid = tid & 31;
    const int wr  = wid >> 1;
    const int wc  = wid & 1;
    const int g   = lid >> 2;
    const int tg  = lid & 3;

    auto load_stage = [&](int buf, int kb) {
        const uint32_t dbase = sa + buf * STAGE;
        const int kc = kb * 64;
#pragma unroll
        for (int i = 0; i < 4; ++i) {               // A: 1024 chunks
            const int t = tid + (i << 8);
            const int row = t >> 3, c = t & 7;
            cp16(dbase + row * 128 + ((c ^ (row & 7)) << 4),
                 Ab + (size_t)row * 512 + kc + c * 8);
        }
        {
            const int t = tid;
            const int row = t >> 3, c = t & 7;
            cp16(dbase + 16384 + row * 128 + ((c ^ (row & 7)) << 4),
                 Bb + (size_t)row * 512 + kc + c * 8);
        }
        {
            const int t = tid + 256;
            const int row = t >> 3, c = t & 7;
            cp16(dbase + 16384 + row * 128 + ((c ^ (row & 7)) << 4),
                 Bb + (size_t)row * 512 + kc + c * 8);
        }
    };

    float acc[2][4][4];
#pragma unroll
    for (int mt = 0; mt < 2; ++mt)
#pragma unroll
        for (int nt = 0; nt < 4; ++nt)
#pragma unroll
            for (int i = 0; i < 4; ++i) acc[mt][nt][i] = 0.0f;

    const uint32_t sx = (uint32_t)(lid & 7) << 4;
    const uint32_t hb = (uint32_t)(lid >> 4) << 4;
    uint32_t ra[2], rb[2];
#pragma unroll
    for (int mt = 0; mt < 2; ++mt)
        ra[mt] = (uint32_t)(wr * 32 + mt * 16 + (lid & 15)) * 128;
#pragma unroll
    for (int n2 = 0; n2 < 2; ++n2)
        rb[n2] = 16384u + (uint32_t)(wc * 32 + n2 * 16 + (lid & 15)) * 128;

    load_stage(0, 0); CP_COMMIT();
    load_stage(1, 1); CP_COMMIT();

#pragma unroll 1
    for (int kb = 0; kb < 8; ++kb) {
        CP_WAIT1();
        __syncthreads();
        if (kb + 2 < 8) load_stage((kb + 2) % 3, kb + 2);
        CP_COMMIT();

        const uint32_t sbase = sa + (kb % 3) * STAGE;

#pragma unroll
        for (int ks = 0; ks < 4; ++ks) {
            const uint32_t cv = (uint32_t)(ks << 5) + hb;

            uint32_t ah[2][4], bb[4][2];
#pragma unroll
            for (int mt = 0; mt < 2; ++mt)
                ldsm4(ah[mt], sbase + ra[mt] + (cv ^ sx));
#pragma unroll
            for (int n2 = 0; n2 < 2; ++n2) {
                uint32_t r[4];
                ldsm4(r, sbase + rb[n2] + (cv ^ sx));
                bb[n2 * 2][0] = r[0]; bb[n2 * 2][1] = r[2];
                bb[n2 * 2 + 1][0] = r[1]; bb[n2 * 2 + 1][1] = r[3];
            }
#pragma unroll
            for (int mt = 0; mt < 2; ++mt)
#pragma unroll
                for (int nt = 0; nt < 4; ++nt) mma16f(acc[mt][nt], ah[mt], bb[nt]);
        }
    }

    const int rbase = rloc0 + wr * 32 + g;
    const int cbase = cloc0 + wc * 32 + tg * 2;
#pragma unroll
    for (int mt = 0; mt < 2; ++mt) {
#pragma unroll
        for (int nt = 0; nt < 4; ++nt) {
            const int r = rbase + mt * 16;
            const int c = cbase + nt * 8;
            if (EPI == 0) {
                *reinterpret_cast<float2*>(&C[(size_t)r * ldc + c]) =
                    make_float2(acc[mt][nt][0], acc[mt][nt][1]);
                *reinterpret_cast<float2*>(&C[(size_t)(r + 8) * ldc + c]) =
                    make_float2(acc[mt][nt][2], acc[mt][nt][3]);
            } else {
                __half2 v0 = __floats2half2_rn(acc[mt][nt][0], acc[mt][nt][1]);
                __half2 v1 = __floats2half2_rn(acc[mt][nt][2], acc[mt][nt][3]);
                *reinterpret_cast<__half2*>(VT + (size_t)r * 512 + c)       = v0;
                *reinterpret_cast<__half2*>(VT + (size_t)(r + 8) * 512 + c) = v1;
            }
        }
    }
}

// ===========================================================================
// GT_h = Wk_h x Wq_h^T per head: GT[f2,f1] = sum_d wk[f2,h*512+d]*wq[f1,h*512+d]
// ===========================================================================
__global__ void __launch_bounds__(256, 3)
gt_mm()
{
    const int h = blockIdx.z;
    gemm_nt_bf16<1>(g_wkh + h * 512, g_wkl + h * 512, 4096,
                    g_wqh + h * 512, g_wql + h * 512, 4096,
                    nullptr, g_GTh + (size_t)h * 262144,
                    g_GTl + (size_t)h * 262144, 512,
                    blockIdx.y, blockIdx.x);
}

// ===========================================================================
// Merged: id<4096 -> Y_z = x_b GT_h^T tile (bf16 planes out);
//         id>=4096 -> proj_v fp16 tile (fused transpose into VT).
// ===========================================================================
__global__ void __launch_bounds__(256, 3)
y_projv()
{
    const int id = blockIdx.x;
    if (id < 4096) {
        const int z  = id >> 5;               // h*16 + b
        const int by = (id >> 3) & 3;
        const int bx = id & 7;
        const int h = z >> 4, b = z & 15;
        gemm_nt_bf16<1>(g_xh + (size_t)b * 262144, g_xl + (size_t)b * 262144, 512,
                        g_GTh + (size_t)h * 262144, g_GTl + (size_t)h * 262144, 512,
                        nullptr, g_Yh + (size_t)z * 262144,
                        g_Yl + (size_t)z * 262144, 512, by, bx);
    } else {
        const int t  = id - 4096;             // 0..4095
        const int vx = t & 127;               // token-tile (64 tokens)
        const int vy = t >> 7;                // d-tile (128 dcols)
        const __half* Ab = g_WV16 + (size_t)vy * 128 * 512;
        const __half* Bb = g_x16  + (size_t)vx * 64 * 512;
        const int hH = vy >> 2, bB = vx >> 3;
        __half* VT = g_VT + (size_t)(hH * 16 + bB) * 262144;
        gemm_nt_f16<1>(Ab, Bb, nullptr, 0, VT,
                       (vy & 3) * 128, (vx & 7) * 64);
    }
}

// ===========================================================================
// logits_z = Y_z x_b^T  (fp32 out to g_P)
// ===========================================================================
__global__ void __launch_bounds__(256, 3)
qk2_mm()
{
    const int z = blockIdx.z;                 // h*16 + b
    const int b = z & 15;
    gemm_nt_bf16<0>(g_Yh + (size_t)z * 262144, g_Yl + (size_t)z * 262144, 512,
                    g_xh + (size_t)b * 262144, g_xl + (size_t)b * 262144, 512,
                    g_P + (size_t)z * 262144, nullptr, nullptr, 512,
                    blockIdx.y, blockIdx.x);
}

// ===========================================================================
// PV GEMM: single fp16 P x single fp16 V, 1 MMA pass. C[128x64] fp32.
// ===========================================================================
__global__ void __launch_bounds__(256, 3)
pv_mm(float* __restrict__ out)
{
    const int z = blockIdx.z;
    const int h = z >> 4, b = z & 15;
    const size_t zo = (size_t)z * 262144;
    const __half* Ab = g_Pf + zo + (size_t)(blockIdx.y * 128) * 512;
    const __half* Bb = g_VT + zo + (size_t)(blockIdx.x * 64) * 512;
    float* C = out + (size_t)b * 512 * 4096 + h * 512;
    gemm_nt_f16<0>(Ab, Bb, C, 4096, nullptr,
                   blockIdx.y * 128, blockIdx.x * 64);
}

// ===========================================================================
// Prep: split x -> (xh,xl,x16); wq -> (wqh,wql); wk -> (wkh,wkl). Flat grid.
// ===========================================================================
__global__ void prep_split(const float* __restrict__ x,
                           const float* __restrict__ wq,
                           const float* __restrict__ wk)
{
    const int id = blockIdx.x;
    if (id < 4096) {
        const size_t i = (size_t)id * 1024 + threadIdx.x * 4;
        const float4 v = *reinterpret_cast<const float4*>(x + i);
        uint32_t h0, l0, h1, l1;
        pack2(v.x, v.y, h0, l0);
        pack2(v.z, v.w, h1, l1);
        *reinterpret_cast<uint2*>(g_xh + i) = make_uint2(h0, h1);
        *reinterpret_cast<uint2*>(g_xl + i) = make_uint2(l0, l1);
        *reinterpret_cast<__half2*>(g_x16 + i)     = __floats2half2_rn(v.x, v.y);
        *reinterpret_cast<__half2*>(g_x16 + i + 2) = __floats2half2_rn(v.z, v.w);
    } else if (id < 6144) {
        const size_t i = (size_t)(id - 4096) * 1024 + threadIdx.x * 4;
        const float4 v = *reinterpret_cast<const float4*>(wq + i);
        uint32_t h0, l0, h1, l1;
        pack2(v.x, v.y, h0, l0);
        pack2(v.z, v.w, h1, l1);
        *reinterpret_cast<uint2*>(g_wqh + i) = make_uint2(h0, h1);
        *reinterpret_cast<uint2*>(g_wql + i) = make_uint2(l0, l1);
    } else {
        const size_t i = (size_t)(id - 6144) * 1024 + threadIdx.x * 4;
        const float4 v = *reinterpret_cast<const float4*>(wk + i);
        uint32_t h0, l0, h1, l1;
        pack2(v.x, v.y, h0, l0);
        pack2(v.z, v.w, h1, l1);
        *reinterpret_cast<uint2*>(g_wkh + i) = make_uint2(h0, h1);
        *reinterpret_cast<uint2*>(g_wkl + i) = make_uint2(l0, l1);
    }
}

// wv [512,4096] -> WV16 [4096,512] fp16 transpose
__global__ void wt_v(const float* __restrict__ wv)
{
    __shared__ float t[32][33];
    const int n0 = blockIdx.x * 32, k0 = blockIdx.y * 32;
    const int tx = threadIdx.x, ty = threadIdx.y;
#pragma unroll
    for (int i = 0; i < 4; ++i)
        t[ty + i * 8][tx] = wv[(size_t)(k0 + ty + i * 8) * 4096 + n0 + tx];
    __syncthreads();
#pragma unroll
    for (int i = 0; i < 4; ++i) {
        const float v = t[tx][ty + i * 8];
        g_WV16[(size_t)(n0 + ty + i * 8) * 512 + k0 + tx] = __float2half_rn(v);
    }
}

// ===========================================================================
// Softmax over rows of g_P (512 wide), writes single fp16 plane g_Pf.
// ===========================================================================
__global__ void softmax_kernel()
{
    const size_t row = blockIdx.x;
    const float* p = g_P + row * 512;
    const int t = threadIdx.x;

    float2 v = reinterpret_cast<const float2*>(p)[t];
    __shared__ float red[8];

    float m = fmaxf(v.x, v.y);
#pragma unroll
    for (int o = 16; o > 0; o >>= 1) m = fmaxf(m, __shfl_xor_sync(0xFFFFFFFFu, m, o));
    if ((t & 31) == 0) red[t >> 5] = m;
    __syncthreads();
    m = red[0];
#pragma unroll
    for (int i = 1; i < 8; i++) m = fmaxf(m, red[i]);
    __syncthreads();

    const float e0 = __expf(v.x - m);
    const float e1 = __expf(v.y - m);

    float s = e0 + e1;
#pragma unroll
    for (int o = 16; o > 0; o >>= 1) s += __shfl_xor_sync(0xFFFFFFFFu, s, o);
    if ((t & 31) == 0) red[t >> 5] = s;
    __syncthreads();
    s = red[0];
#pragma unroll
    for (int i = 1; i < 8; i++) s += red[i];

    const float inv = 1.0f / s;
    reinterpret_cast<__half2*>(g_Pf + row * 512)[t] =
        __floats2half2_rn(e0 * inv, e1 * inv);
}

// ===========================================================================
// Launch
// ===========================================================================
extern "C" void kernel_launch(void* const* d_in, const int* in_sizes, int n_in,
                              void* d_out, int out_size)
{
    const float* x  = (const float*)d_in[0];
    const float* wq = (const float*)d_in[1];
    const float* wk = (const float*)d_in[2];
    const float* wv = (const float*)d_in[3];
    float* out = (float*)d_out;

    cudaFuncSetAttribute(gt_mm,   cudaFuncAttributeMaxDynamicSharedMemorySize, GEMM_SMEM);
    cudaFuncSetAttribute(y_projv, cudaFuncAttributeMaxDynamicSharedMemorySize, GEMM_SMEM);
    cudaFuncSetAttribute(qk2_mm,  cudaFuncAttributeMaxDynamicSharedMemorySize, GEMM_SMEM);
    cudaFuncSetAttribute(pv_mm,   cudaFuncAttributeMaxDynamicSharedMemorySize, GEMM_SMEM);

    prep_split<<<8192, 256>>>(x, wq, wk);                        // 1
    wt_v<<<dim3(128, 16), dim3(32, 8)>>>(wv);                    // 2
    gt_mm<<<dim3(8, 4, 8), 256, GEMM_SMEM>>>();                  // 3
    y_projv<<<8192, 256, GEMM_SMEM>>>();                         // 4 <- profiled
    qk2_mm<<<dim3(8, 4, 128), 256, GEMM_SMEM>>>();               // 5
    softmax_kernel<<<65536, 256>>>();                            // 6
    pv_mm<<<dim3(8, 4, 128), 256, GEMM_SMEM>>>(out);             // 7
}